// round 15
// baseline (speedup 1.0000x reference)
#include <cuda_runtime.h>
#include <cuda_bf16.h>
#include <cuda_fp16.h>
#include <cstdint>

// Problem constants
#define B_   4
#define S_   2048
#define D_   512
#define H_   8
#define DK_  64
#define BH_  (B_ * H_)      // 32
#define M_   (B_ * S_)      // 8192
// SCALE * log2(e), folded into Q at projection epilogue
#define QSCALE_ (0.18033688011112042f)
#define ONES_F16X2 0x3C003C00u

// fp16 operands (device globals; no allocs allowed)
__device__ __half g_xf[M_ * D_];                  // x single fp16
__device__ __half g_w[3 * D_ * D_];               // Wq,Wk,Wv single fp16
// Attention operands: Q (pre-scaled), K, V — all single fp16
__device__ __half g_qf[BH_ * S_ * DK_];
__device__ __half g_kh[BH_ * S_ * DK_];
__device__ __half g_vh[BH_ * S_ * DK_];

// ---------------------------------------------------------------------------
// helpers
// ---------------------------------------------------------------------------
__device__ __forceinline__ uint32_t pack_f16x2(float x, float y) {
    __half2 h = __floats2half2_rn(x, y);
    return *(uint32_t*)&h;
}
__device__ __forceinline__ uint32_t ex2_f16x2(uint32_t x) {
    uint32_t r;
    asm("ex2.approx.f16x2 %0, %1;" : "=r"(r) : "r"(x));
    return r;
}
__device__ __forceinline__ uint32_t smem_u32(const void* p) {
    uint32_t a;
    asm("{ .reg .u64 t; cvta.to.shared.u64 t, %1; cvt.u32.u64 %0, t; }"
        : "=r"(a) : "l"(p));
    return a;
}
__device__ __forceinline__ void mma_f16(float c[4],
        uint32_t a0, uint32_t a1, uint32_t a2, uint32_t a3,
        uint32_t b0, uint32_t b1) {
    asm volatile(
        "mma.sync.aligned.m16n8k16.row.col.f32.f16.f16.f32 "
        "{%0,%1,%2,%3}, {%4,%5,%6,%7}, {%8,%9}, {%0,%1,%2,%3};"
        : "+f"(c[0]), "+f"(c[1]), "+f"(c[2]), "+f"(c[3])
        : "r"(a0), "r"(a1), "r"(a2), "r"(a3), "r"(b0), "r"(b1));
}
__device__ __forceinline__ void ldm_x4(uint32_t& r0, uint32_t& r1,
                                       uint32_t& r2, uint32_t& r3, uint32_t addr) {
    asm volatile("ldmatrix.sync.aligned.m8n8.x4.shared.b16 {%0,%1,%2,%3}, [%4];"
        : "=r"(r0), "=r"(r1), "=r"(r2), "=r"(r3) : "r"(addr));
}
__device__ __forceinline__ void ldm_x4_t(uint32_t& r0, uint32_t& r1,
                                         uint32_t& r2, uint32_t& r3, uint32_t addr) {
    asm volatile("ldmatrix.sync.aligned.m8n8.x4.trans.shared.b16 {%0,%1,%2,%3}, [%4];"
        : "=r"(r0), "=r"(r1), "=r"(r2), "=r"(r3) : "r"(addr));
}
__device__ __forceinline__ void cp16(uint32_t dst, const void* src) {
    asm volatile("cp.async.cg.shared.global [%0], [%1], 16;"
        :: "r"(dst), "l"(src) : "memory");
}
#define CP_COMMIT() asm volatile("cp.async.commit_group;" ::: "memory")
#define CP_WAIT0()  asm volatile("cp.async.wait_group 0;" ::: "memory")

// ---------------------------------------------------------------------------
// Kernel 0: fused prep — convert x and Wq/Wk/Wv to single fp16.
// ---------------------------------------------------------------------------
#define N4X (M_ * D_ / 4)
#define N4W (D_ * D_ / 4)

__global__ __launch_bounds__(256) void prep_kernel(
    const float* __restrict__ x,  const float* __restrict__ wq,
    const float* __restrict__ wk, const float* __restrict__ wv)
{
    int i = blockIdx.x * 256 + threadIdx.x;
    if (i < N4X) {
        float4 v = ((const float4*)x)[i];
        ((uint2*)g_xf)[i] = make_uint2(pack_f16x2(v.x, v.y), pack_f16x2(v.z, v.w));
    } else {
        int j = i - N4X;
        if (j >= 3 * N4W) return;
        int z = j / N4W, jz = j - z * N4W;
        const float* w = (z == 0) ? wq : (z == 1) ? wk : wv;
        float4 v = ((const float4*)w)[jz];
        ((uint2*)(g_w + z * D_ * D_))[jz] =
            make_uint2(pack_f16x2(v.x, v.y), pack_f16x2(v.z, v.w));
    }
}

// ---------------------------------------------------------------------------
// Kernel 1: QKV projection, m32/warp, z per gridIdx.z (W-frag reuse x4).
// block 128 (4 warps x m32 = 128-row m-tile), grid (M/128=64, H=8, 3).
// Single-term fp16, identical per-output accumulation order to R14.
// ---------------------------------------------------------------------------
#define QKV_X  0                // 128 rows * 144B
#define QKV_W  18432            // 64 rows * 144B
#define QKV_STAGE 27648
#define QKV_SMEM (2 * QKV_STAGE)  // 55296

__global__ __launch_bounds__(128) void qkv_mma_kernel()
{
    extern __shared__ char sm[];
    const uint32_t sb = smem_u32(sm);
    const int tid = threadIdx.x, wid = tid >> 5, lane = tid & 31;
    const int g = lane >> 2, c4 = lane & 3;
    const int m0 = blockIdx.x * 128;
    const int h  = blockIdx.y;
    const int z  = blockIdx.z;
    const int n0 = h * 64;

    const __half* wz = g_w + z * D_ * D_;

    const uint32_t aAddr0 = (uint32_t)((wid * 32 + (lane & 15)) * 144 + (lane >> 4) * 16);
    const uint32_t aAddr1 = aAddr0 + 16 * 144;
    const uint32_t bAddr = (uint32_t)(QKV_W + (lane >> 4) * 1152
                                      + (lane & 7) * 144 + ((lane >> 3) & 1) * 16);

    float o[2][8][4];
#pragma unroll
    for (int rb = 0; rb < 2; rb++)
#pragma unroll
        for (int i = 0; i < 8; i++)
#pragma unroll
            for (int j = 0; j < 4; j++) o[rb][i][j] = 0.0f;

    auto copy_stage = [&](int st, int buf) {
        const uint32_t base = sb + buf * QKV_STAGE;
#pragma unroll
        for (int c = tid; c < 1536; c += 128) {
            const void* src;
            uint32_t dst;
            if (c < 1024) {
                int row = c >> 3, seg = c & 7;
                src = g_xf + (m0 + row) * D_ + st * 64 + seg * 8;
                dst = base + QKV_X + row * 144 + seg * 16;
            } else {
                int cc = c - 1024, row = cc >> 3, seg = cc & 7;
                src = wz + (n0 + row) * D_ + st * 64 + seg * 8;
                dst = base + QKV_W + row * 144 + seg * 16;
            }
            cp16(dst, src);
        }
    };

    copy_stage(0, 0);
    CP_COMMIT();

    for (int st = 0; st < 8; st++) {
        CP_WAIT0();
        __syncthreads();
        if (st < 7) { copy_stage(st + 1, (st + 1) & 1); CP_COMMIT(); }
        const uint32_t base = sb + (st & 1) * QKV_STAGE;
#pragma unroll
        for (int ks = 0; ks < 4; ks++) {
            uint32_t a0[4], a1[4];
            ldm_x4(a0[0], a0[1], a0[2], a0[3], base + QKV_X + aAddr0 + ks * 32);
            ldm_x4(a1[0], a1[1], a1[2], a1[3], base + QKV_X + aAddr1 + ks * 32);
#pragma unroll
            for (int p = 0; p < 4; p++) {
                uint32_t b0a, b1a, b0b, b1b;
                ldm_x4(b0a, b1a, b0b, b1b, base + bAddr + p * 2304 + ks * 32);
                mma_f16(o[0][2 * p],     a0[0], a0[1], a0[2], a0[3], b0a, b1a);
                mma_f16(o[0][2 * p + 1], a0[0], a0[1], a0[2], a0[3], b0b, b1b);
                mma_f16(o[1][2 * p],     a1[0], a1[1], a1[2], a1[3], b0a, b1a);
                mma_f16(o[1][2 * p + 1], a1[0], a1[1], a1[2], a1[3], b0b, b1b);
            }
        }
    }

    // epilogue: scatter to [bh][s][dk] fp16 (Q pre-scaled)
#pragma unroll
    for (int rb = 0; rb < 2; rb++) {
        const int r0 = m0 + wid * 32 + rb * 16 + g;
        const int r1 = r0 + 8;
        const int b0i = r0 >> 11, s0 = r0 & 2047;
        const int b1i = r1 >> 11, s1 = r1 & 2047;
        const long base0 = ((long)(b0i * H_ + h) * S_ + s0) * DK_;
        const long base1 = ((long)(b1i * H_ + h) * S_ + s1) * DK_;
#pragma unroll
        for (int nt = 0; nt < 8; nt++) {
            const int dk = nt * 8 + c4 * 2;
            if (z == 0) {
                *(uint32_t*)&g_qf[base0 + dk] =
                    pack_f16x2(o[rb][nt][0] * QSCALE_, o[rb][nt][1] * QSCALE_);
                *(uint32_t*)&g_qf[base1 + dk] =
                    pack_f16x2(o[rb][nt][2] * QSCALE_, o[rb][nt][3] * QSCALE_);
            } else {
                __half* dst = (z == 1) ? g_kh : g_vh;
                *(uint32_t*)&dst[base0 + dk] = pack_f16x2(o[rb][nt][0], o[rb][nt][1]);
                *(uint32_t*)&dst[base1 + dk] = pack_f16x2(o[rb][nt][2], o[rb][nt][3]);
            }
        }
    }
}

// ---------------------------------------------------------------------------
// Kernel 2: attention, TK=128, software-pipelined: phase A of group p+1
// issues before exp(p), so MUFU exp overlaps tensor work. Pure issue-order
// change vs R14 — arithmetic identical.
// grid (S/128=16, BH=32), block 128 (4 warps x m32).
// ---------------------------------------------------------------------------
#define AT_K 0
#define AT_V 18432              // 128 rows * 144B
#define AT_STAGE 36864
#define AT_SMEM (2 * AT_STAGE)  // 73728

__global__ __launch_bounds__(128, 2) void attn_mma_kernel(float* __restrict__ out)
{
    extern __shared__ char sm[];
    const uint32_t sb = smem_u32(sm);
    const int tid = threadIdx.x, wid = tid >> 5, lane = tid & 31;
    const int g = lane >> 2, c4 = lane & 3;
    const int bh = blockIdx.y;
    const int q0 = blockIdx.x * 128;

    const __half* Khg = g_kh + (long)bh * S_ * DK_;
    const __half* Vhg = g_vh + (long)bh * S_ * DK_;
    const __half* Qfg = g_qf + (long)bh * S_ * DK_;

    auto copy_tiles = [&](int kt, int buf) {
        const uint32_t base = sb + buf * AT_STAGE;
#pragma unroll
        for (int c = tid; c < 2048; c += 128) {
            int arr = c >> 10, cc = c & 1023, row = cc >> 3, seg = cc & 7;
            const __half* src = arr ? Vhg : Khg;
            cp16(base + arr * 18432 + row * 144 + seg * 16,
                 src + (kt * 128 + row) * DK_ + seg * 8);
        }
    };

    copy_tiles(0, 0);
    CP_COMMIT();

    uint32_t qf[2][4][4];
#pragma unroll
    for (int rb = 0; rb < 2; rb++) {
        const int r0 = q0 + wid * 32 + rb * 16 + g;
#pragma unroll
        for (int ks = 0; ks < 4; ks++) {
            const int col = ks * 16 + c4 * 2;
            qf[rb][ks][0] = *(const uint32_t*)&Qfg[r0 * DK_ + col];
            qf[rb][ks][1] = *(const uint32_t*)&Qfg[(r0 + 8) * DK_ + col];
            qf[rb][ks][2] = *(const uint32_t*)&Qfg[r0 * DK_ + col + 8];
            qf[rb][ks][3] = *(const uint32_t*)&Qfg[(r0 + 8) * DK_ + col + 8];
        }
    }

    const uint32_t pA = (uint32_t)((lane >> 4) * 1152 + (lane & 7) * 144
                                   + ((lane >> 3) & 1) * 16);
    const uint32_t pB = (uint32_t)(AT_V + (lane & 15) * 144 + (lane >> 4) * 16);

    float o[2][8][4];
#pragma unroll
    for (int rb = 0; rb < 2; rb++)
#pragma unroll
        for (int i = 0; i < 8; i++)
#pragma unroll
            for (int j = 0; j < 4; j++) o[rb][i][j] = 0.0f;
    float dacc[2][4];
#pragma unroll
    for (int rb = 0; rb < 2; rb++)
#pragma unroll
        for (int j = 0; j < 4; j++) dacc[rb][j] = 0.0f;

    // phase-A helper: compute scores for key-group p into e
    auto phaseA = [&](const uint32_t base, int p, float e[2][2][4]) {
#pragma unroll
        for (int rb = 0; rb < 2; rb++)
#pragma unroll
            for (int n = 0; n < 2; n++)
#pragma unroll
                for (int j = 0; j < 4; j++) e[rb][n][j] = 0.0f;
#pragma unroll
        for (int ks = 0; ks < 4; ks++) {
            uint32_t b0a, b1a, b0b, b1b;
            ldm_x4(b0a, b1a, b0b, b1b, base + AT_K + pA + p * 2304 + ks * 32);
#pragma unroll
            for (int rb = 0; rb < 2; rb++) {
                mma_f16(e[rb][0], qf[rb][ks][0], qf[rb][ks][1], qf[rb][ks][2], qf[rb][ks][3], b0a, b1a);
                mma_f16(e[rb][1], qf[rb][ks][0], qf[rb][ks][1], qf[rb][ks][2], qf[rb][ks][3], b0b, b1b);
            }
        }
    };

    for (int kt = 0; kt < S_ / 128; kt++) {
        CP_WAIT0();
        __syncthreads();
        if (kt < 15) { copy_tiles(kt + 1, (kt + 1) & 1); CP_COMMIT(); }
        const uint32_t base = sb + (kt & 1) * AT_STAGE;

        float eC[2][2][4];
        phaseA(base, 0, eC);

#pragma unroll
        for (int p = 0; p < 8; p++) {
            float eN[2][2][4];
            if (p < 7) phaseA(base, p + 1, eN);   // tensor work overlaps exp below

            // exp + pack (MUFU/ALU, runs under phase-A(p+1) tensor latency)
            uint32_t ph[2][4];
#pragma unroll
            for (int rb = 0; rb < 2; rb++) {
                ph[rb][0] = ex2_f16x2(pack_f16x2(eC[rb][0][0], eC[rb][0][1]));
                ph[rb][1] = ex2_f16x2(pack_f16x2(eC[rb][0][2], eC[rb][0][3]));
                ph[rb][2] = ex2_f16x2(pack_f16x2(eC[rb][1][0], eC[rb][1][1]));
                ph[rb][3] = ex2_f16x2(pack_f16x2(eC[rb][1][2], eC[rb][1][3]));
                mma_f16(dacc[rb], ph[rb][0], ph[rb][1], ph[rb][2], ph[rb][3],
                        ONES_F16X2, ONES_F16X2);
            }

            // PV for key-group p
#pragma unroll
            for (int pp = 0; pp < 4; pp++) {
                uint32_t b0a, b1a, b0b, b1b;
                ldm_x4_t(b0a, b1a, b0b, b1b, base + pB + p * 2304 + pp * 32);
#pragma unroll
                for (int rb = 0; rb < 2; rb++) {
                    mma_f16(o[rb][2 * pp],     ph[rb][0], ph[rb][1], ph[rb][2], ph[rb][3], b0a, b1a);
                    mma_f16(o[rb][2 * pp + 1], ph[rb][0], ph[rb][1], ph[rb][2], ph[rb][3], b0b, b1b);
                }
            }

            if (p < 7) {
#pragma unroll
                for (int rb = 0; rb < 2; rb++)
#pragma unroll
                    for (int n = 0; n < 2; n++)
#pragma unroll
                        for (int j = 0; j < 4; j++) eC[rb][n][j] = eN[rb][n][j];
            }
        }
    }

    const int b = bh >> 3, h = bh & 7;
#pragma unroll
    for (int rb = 0; rb < 2; rb++) {
        const float inv0 = 1.0f / (dacc[rb][0] + 1e-8f);
        const float inv1 = 1.0f / (dacc[rb][2] + 1e-8f);

        const int q_r0 = q0 + wid * 32 + rb * 16 + g;
        float* op0 = &out[((long)(b * S_ + q_r0)) * D_ + h * 64];
        float* op1 = &out[((long)(b * S_ + q_r0 + 8)) * D_ + h * 64];
#pragma unroll
        for (int nt = 0; nt < 8; nt++) {
            const int dk = nt * 8 + c4 * 2;
            *(float2*)&op0[dk] = make_float2(o[rb][nt][0] * inv0, o[rb][nt][1] * inv0);
            *(float2*)&op1[dk] = make_float2(o[rb][nt][2] * inv1, o[rb][nt][3] * inv1);
        }
    }
}

// ---------------------------------------------------------------------------
extern "C" void kernel_launch(void* const* d_in, const int* in_sizes, int n_in,
                              void* d_out, int out_size)
{
    const float* x  = (const float*)d_in[0];
    const float* wq = (const float*)d_in[1];
    const float* wk = (const float*)d_in[2];
    const float* wv = (const float*)d_in[3];
    float* out = (float*)d_out;

    cudaFuncSetAttribute(qkv_mma_kernel,
                         cudaFuncAttributeMaxDynamicSharedMemorySize, QKV_SMEM);
    cudaFuncSetAttribute(attn_mma_kernel,
                         cudaFuncAttributeMaxDynamicSharedMemorySize, AT_SMEM);

    const int ntot = N4X + 3 * N4W;
    prep_kernel<<<(ntot + 255) / 256, 256>>>(x, wq, wk, wv);
    qkv_mma_kernel<<<dim3(M_ / 128, H_, 3), 128, QKV_SMEM>>>();
    attn_mma_kernel<<<dim3(S_ / 128, BH_), 128, AT_SMEM>>>(out);
}

// round 16
// speedup vs baseline: 1.0300x; 1.0300x over previous
#include <cuda_runtime.h>
#include <cuda_bf16.h>
#include <cuda_fp16.h>
#include <cstdint>

// Problem constants
#define B_   4
#define S_   2048
#define D_   512
#define H_   8
#define DK_  64
#define BH_  (B_ * H_)      // 32
#define M_   (B_ * S_)      // 8192
// SCALE * log2(e), folded into Q at projection epilogue
#define QSCALE_ (0.18033688011112042f)
#define ONES_F16X2 0x3C003C00u

// fp16 operands (device globals; no allocs allowed)
__device__ __half g_xf[M_ * D_];                  // x single fp16
__device__ __half g_w[3 * D_ * D_];               // Wq,Wk,Wv single fp16
// Attention operands: Q (pre-scaled), K, V — all single fp16
__device__ __half g_qf[BH_ * S_ * DK_];
__device__ __half g_kh[BH_ * S_ * DK_];
__device__ __half g_vh[BH_ * S_ * DK_];

// ---------------------------------------------------------------------------
// helpers
// ---------------------------------------------------------------------------
__device__ __forceinline__ uint32_t pack_f16x2(float x, float y) {
    __half2 h = __floats2half2_rn(x, y);
    return *(uint32_t*)&h;
}
__device__ __forceinline__ uint32_t ex2_f16x2(uint32_t x) {
    uint32_t r;
    asm("ex2.approx.f16x2 %0, %1;" : "=r"(r) : "r"(x));
    return r;
}
__device__ __forceinline__ uint32_t smem_u32(const void* p) {
    uint32_t a;
    asm("{ .reg .u64 t; cvta.to.shared.u64 t, %1; cvt.u32.u64 %0, t; }"
        : "=r"(a) : "l"(p));
    return a;
}
// fp32-accumulator HMMA
__device__ __forceinline__ void mma_f16(float c[4],
        uint32_t a0, uint32_t a1, uint32_t a2, uint32_t a3,
        uint32_t b0, uint32_t b1) {
    asm volatile(
        "mma.sync.aligned.m16n8k16.row.col.f32.f16.f16.f32 "
        "{%0,%1,%2,%3}, {%4,%5,%6,%7}, {%8,%9}, {%0,%1,%2,%3};"
        : "+f"(c[0]), "+f"(c[1]), "+f"(c[2]), "+f"(c[3])
        : "r"(a0), "r"(a1), "r"(a2), "r"(a3), "r"(b0), "r"(b1));
}
// fp16-accumulator HMMA (C/D are 2 regs of packed f16x2: d0={r, c2,c2+1}, d1={r+8,...})
__device__ __forceinline__ void mma_f16_h(uint32_t c[2],
        uint32_t a0, uint32_t a1, uint32_t a2, uint32_t a3,
        uint32_t b0, uint32_t b1) {
    asm volatile(
        "mma.sync.aligned.m16n8k16.row.col.f16.f16.f16.f16 "
        "{%0,%1}, {%2,%3,%4,%5}, {%6,%7}, {%0,%1};"
        : "+r"(c[0]), "+r"(c[1])
        : "r"(a0), "r"(a1), "r"(a2), "r"(a3), "r"(b0), "r"(b1));
}
__device__ __forceinline__ void ldm_x4(uint32_t& r0, uint32_t& r1,
                                       uint32_t& r2, uint32_t& r3, uint32_t addr) {
    asm volatile("ldmatrix.sync.aligned.m8n8.x4.shared.b16 {%0,%1,%2,%3}, [%4];"
        : "=r"(r0), "=r"(r1), "=r"(r2), "=r"(r3) : "r"(addr));
}
__device__ __forceinline__ void ldm_x4_t(uint32_t& r0, uint32_t& r1,
                                         uint32_t& r2, uint32_t& r3, uint32_t addr) {
    asm volatile("ldmatrix.sync.aligned.m8n8.x4.trans.shared.b16 {%0,%1,%2,%3}, [%4];"
        : "=r"(r0), "=r"(r1), "=r"(r2), "=r"(r3) : "r"(addr));
}
__device__ __forceinline__ void cp16(uint32_t dst, const void* src) {
    asm volatile("cp.async.cg.shared.global [%0], [%1], 16;"
        :: "r"(dst), "l"(src) : "memory");
}
#define CP_COMMIT() asm volatile("cp.async.commit_group;" ::: "memory")
#define CP_WAIT0()  asm volatile("cp.async.wait_group 0;" ::: "memory")

// ---------------------------------------------------------------------------
// Kernel 0: fused prep — convert x and Wq/Wk/Wv to single fp16.
// ---------------------------------------------------------------------------
#define N4X (M_ * D_ / 4)
#define N4W (D_ * D_ / 4)

__global__ __launch_bounds__(256) void prep_kernel(
    const float* __restrict__ x,  const float* __restrict__ wq,
    const float* __restrict__ wk, const float* __restrict__ wv)
{
    int i = blockIdx.x * 256 + threadIdx.x;
    if (i < N4X) {
        float4 v = ((const float4*)x)[i];
        ((uint2*)g_xf)[i] = make_uint2(pack_f16x2(v.x, v.y), pack_f16x2(v.z, v.w));
    } else {
        int j = i - N4X;
        if (j >= 3 * N4W) return;
        int z = j / N4W, jz = j - z * N4W;
        const float* w = (z == 0) ? wq : (z == 1) ? wk : wv;
        float4 v = ((const float4*)w)[jz];
        ((uint2*)(g_w + z * D_ * D_))[jz] =
            make_uint2(pack_f16x2(v.x, v.y), pack_f16x2(v.z, v.w));
    }
}

// ---------------------------------------------------------------------------
// Kernel 1: QKV projection, z-folded, single-term fp16 (unchanged from R14).
// block 128 (4 warps x m16), grid (M/64=128, H=8).
// ---------------------------------------------------------------------------
#define QKV_X  0                // 64 rows * 144B
#define QKV_W  9216             // 3 slices of 64 rows * 144B
#define QKV_STAGE 36864
#define QKV_SMEM (2 * QKV_STAGE)  // 73728

__global__ __launch_bounds__(128) void qkv_mma_kernel()
{
    extern __shared__ char sm[];
    const uint32_t sb = smem_u32(sm);
    const int tid = threadIdx.x, wid = tid >> 5, lane = tid & 31;
    const int g = lane >> 2, c4 = lane & 3;
    const int m0 = blockIdx.x * 64;
    const int h  = blockIdx.y;
    const int n0 = h * 64;

    const uint32_t aAddr = (uint32_t)((wid * 16 + (lane & 15)) * 144 + (lane >> 4) * 16);
    const uint32_t bAddr = (uint32_t)(QKV_W + (lane >> 4) * 1152
                                      + (lane & 7) * 144 + ((lane >> 3) & 1) * 16);

    float o[3][8][4];
#pragma unroll
    for (int z = 0; z < 3; z++)
#pragma unroll
        for (int i = 0; i < 8; i++)
#pragma unroll
            for (int j = 0; j < 4; j++) o[z][i][j] = 0.0f;

    auto copy_stage = [&](int st, int buf) {
        const uint32_t base = sb + buf * QKV_STAGE;
#pragma unroll
        for (int c = tid; c < 2048; c += 128) {
            const void* src;
            uint32_t dst;
            if (c < 512) {
                int row = c >> 3, seg = c & 7;
                src = g_xf + (m0 + row) * D_ + st * 64 + seg * 8;
                dst = base + QKV_X + row * 144 + seg * 16;
            } else {
                int j = c - 512, z = j >> 9, cc = j & 511, row = cc >> 3, seg = cc & 7;
                src = g_w + z * D_ * D_ + (n0 + row) * D_ + st * 64 + seg * 8;
                dst = base + QKV_W + z * 9216 + row * 144 + seg * 16;
            }
            cp16(dst, src);
        }
    };

    copy_stage(0, 0);
    CP_COMMIT();

    for (int st = 0; st < 8; st++) {
        CP_WAIT0();
        __syncthreads();
        if (st < 7) { copy_stage(st + 1, (st + 1) & 1); CP_COMMIT(); }
        const uint32_t base = sb + (st & 1) * QKV_STAGE;
#pragma unroll
        for (int ks = 0; ks < 4; ks++) {
            uint32_t ah[4];
            ldm_x4(ah[0], ah[1], ah[2], ah[3], base + QKV_X + aAddr + ks * 32);
#pragma unroll
            for (int z = 0; z < 3; z++) {
#pragma unroll
                for (int p = 0; p < 4; p++) {
                    uint32_t b0a, b1a, b0b, b1b;
                    ldm_x4(b0a, b1a, b0b, b1b,
                           base + bAddr + z * 9216 + p * 2304 + ks * 32);
                    mma_f16(o[z][2 * p],     ah[0], ah[1], ah[2], ah[3], b0a, b1a);
                    mma_f16(o[z][2 * p + 1], ah[0], ah[1], ah[2], ah[3], b0b, b1b);
                }
            }
        }
    }

    const int r0 = m0 + wid * 16 + g;
    const int r1 = r0 + 8;
    const int b0i = r0 >> 11, s0 = r0 & 2047;
    const int b1i = r1 >> 11, s1 = r1 & 2047;
    const long base0 = ((long)(b0i * H_ + h) * S_ + s0) * DK_;
    const long base1 = ((long)(b1i * H_ + h) * S_ + s1) * DK_;
#pragma unroll
    for (int z = 0; z < 3; z++) {
#pragma unroll
        for (int nt = 0; nt < 8; nt++) {
            const int dk = nt * 8 + c4 * 2;
            if (z == 0) {
                *(uint32_t*)&g_qf[base0 + dk] =
                    pack_f16x2(o[0][nt][0] * QSCALE_, o[0][nt][1] * QSCALE_);
                *(uint32_t*)&g_qf[base1 + dk] =
                    pack_f16x2(o[0][nt][2] * QSCALE_, o[0][nt][3] * QSCALE_);
            } else {
                __half* dst = (z == 1) ? g_kh : g_vh;
                *(uint32_t*)&dst[base0 + dk] = pack_f16x2(o[z][nt][0], o[z][nt][1]);
                *(uint32_t*)&dst[base1 + dk] = pack_f16x2(o[z][nt][2], o[z][nt][3]);
            }
        }
    }
}

// ---------------------------------------------------------------------------
// Kernel 2: attention, TK=128 (R14 structure). Phase A now uses fp16-acc
// HMMA: scores land packed f16x2 and feed ex2.f16x2 directly (no packs).
// PV and denominator keep fp32 accumulators.
// grid (S/128=16, BH=32), block 128 (4 warps x m32).
// ---------------------------------------------------------------------------
#define AT_K 0
#define AT_V 18432              // 128 rows * 144B
#define AT_STAGE 36864
#define AT_SMEM (2 * AT_STAGE)  // 73728

__global__ __launch_bounds__(128, 2) void attn_mma_kernel(float* __restrict__ out)
{
    extern __shared__ char sm[];
    const uint32_t sb = smem_u32(sm);
    const int tid = threadIdx.x, wid = tid >> 5, lane = tid & 31;
    const int g = lane >> 2, c4 = lane & 3;
    const int bh = blockIdx.y;
    const int q0 = blockIdx.x * 128;

    const __half* Khg = g_kh + (long)bh * S_ * DK_;
    const __half* Vhg = g_vh + (long)bh * S_ * DK_;
    const __half* Qfg = g_qf + (long)bh * S_ * DK_;

    auto copy_tiles = [&](int kt, int buf) {
        const uint32_t base = sb + buf * AT_STAGE;
#pragma unroll
        for (int c = tid; c < 2048; c += 128) {
            int arr = c >> 10, cc = c & 1023, row = cc >> 3, seg = cc & 7;
            const __half* src = arr ? Vhg : Khg;
            cp16(base + arr * 18432 + row * 144 + seg * 16,
                 src + (kt * 128 + row) * DK_ + seg * 8);
        }
    };

    copy_tiles(0, 0);
    CP_COMMIT();

    uint32_t qf[2][4][4];
#pragma unroll
    for (int rb = 0; rb < 2; rb++) {
        const int r0 = q0 + wid * 32 + rb * 16 + g;
#pragma unroll
        for (int ks = 0; ks < 4; ks++) {
            const int col = ks * 16 + c4 * 2;
            qf[rb][ks][0] = *(const uint32_t*)&Qfg[r0 * DK_ + col];
            qf[rb][ks][1] = *(const uint32_t*)&Qfg[(r0 + 8) * DK_ + col];
            qf[rb][ks][2] = *(const uint32_t*)&Qfg[r0 * DK_ + col + 8];
            qf[rb][ks][3] = *(const uint32_t*)&Qfg[(r0 + 8) * DK_ + col + 8];
        }
    }

    const uint32_t pA = (uint32_t)((lane >> 4) * 1152 + (lane & 7) * 144
                                   + ((lane >> 3) & 1) * 16);
    const uint32_t pB = (uint32_t)(AT_V + (lane & 15) * 144 + (lane >> 4) * 16);

    float o[2][8][4];
#pragma unroll
    for (int rb = 0; rb < 2; rb++)
#pragma unroll
        for (int i = 0; i < 8; i++)
#pragma unroll
            for (int j = 0; j < 4; j++) o[rb][i][j] = 0.0f;
    float dacc[2][4];
#pragma unroll
    for (int rb = 0; rb < 2; rb++)
#pragma unroll
        for (int j = 0; j < 4; j++) dacc[rb][j] = 0.0f;

    for (int kt = 0; kt < S_ / 128; kt++) {
        CP_WAIT0();
        __syncthreads();
        if (kt < 15) { copy_tiles(kt + 1, (kt + 1) & 1); CP_COMMIT(); }
        const uint32_t base = sb + (kt & 1) * AT_STAGE;

#pragma unroll
        for (int p = 0; p < 8; p++) {
            // --- phase A: scores in fp16 accumulators (packed f16x2) ---
            // eh[rb][n][d]: n=0 -> keys 0-7 of group, n=1 -> keys 8-15;
            // d=0 -> row g, d=1 -> row g+8. Zero bits == f16x2 zeros.
            uint32_t eh[2][2][2];
#pragma unroll
            for (int rb = 0; rb < 2; rb++)
#pragma unroll
                for (int n = 0; n < 2; n++) {
                    eh[rb][n][0] = 0u;
                    eh[rb][n][1] = 0u;
                }

#pragma unroll
            for (int ks = 0; ks < 4; ks++) {
                uint32_t b0a, b1a, b0b, b1b;
                ldm_x4(b0a, b1a, b0b, b1b, base + AT_K + pA + p * 2304 + ks * 32);
#pragma unroll
                for (int rb = 0; rb < 2; rb++) {
                    mma_f16_h(eh[rb][0], qf[rb][ks][0], qf[rb][ks][1], qf[rb][ks][2], qf[rb][ks][3], b0a, b1a);
                    mma_f16_h(eh[rb][1], qf[rb][ks][0], qf[rb][ks][1], qf[rb][ks][2], qf[rb][ks][3], b0b, b1b);
                }
            }

            // --- exp directly on packed f16x2 accumulators; denom via ones ---
            // PV A-frag order: a0 = row g keys 0-7, a1 = row g+8 keys 0-7,
            //                  a2 = row g keys 8-15, a3 = row g+8 keys 8-15.
            uint32_t ph[2][4];
#pragma unroll
            for (int rb = 0; rb < 2; rb++) {
                ph[rb][0] = ex2_f16x2(eh[rb][0][0]);
                ph[rb][1] = ex2_f16x2(eh[rb][0][1]);
                ph[rb][2] = ex2_f16x2(eh[rb][1][0]);
                ph[rb][3] = ex2_f16x2(eh[rb][1][1]);
                mma_f16(dacc[rb], ph[rb][0], ph[rb][1], ph[rb][2], ph[rb][3],
                        ONES_F16X2, ONES_F16X2);
            }

            // --- PV for key-group p (fp32 accumulators) ---
#pragma unroll
            for (int pp = 0; pp < 4; pp++) {
                uint32_t b0a, b1a, b0b, b1b;
                ldm_x4_t(b0a, b1a, b0b, b1b, base + pB + p * 2304 + pp * 32);
#pragma unroll
                for (int rb = 0; rb < 2; rb++) {
                    mma_f16(o[rb][2 * pp],     ph[rb][0], ph[rb][1], ph[rb][2], ph[rb][3], b0a, b1a);
                    mma_f16(o[rb][2 * pp + 1], ph[rb][0], ph[rb][1], ph[rb][2], ph[rb][3], b0b, b1b);
                }
            }
        }
    }

    const int b = bh >> 3, h = bh & 7;
#pragma unroll
    for (int rb = 0; rb < 2; rb++) {
        const float inv0 = 1.0f / (dacc[rb][0] + 1e-8f);
        const float inv1 = 1.0f / (dacc[rb][2] + 1e-8f);

        const int q_r0 = q0 + wid * 32 + rb * 16 + g;
        float* op0 = &out[((long)(b * S_ + q_r0)) * D_ + h * 64];
        float* op1 = &out[((long)(b * S_ + q_r0 + 8)) * D_ + h * 64];
#pragma unroll
        for (int nt = 0; nt < 8; nt++) {
            const int dk = nt * 8 + c4 * 2;
            *(float2*)&op0[dk] = make_float2(o[rb][nt][0] * inv0, o[rb][nt][1] * inv0);
            *(float2*)&op1[dk] = make_float2(o[rb][nt][2] * inv1, o[rb][nt][3] * inv1);
        }
    }
}

// ---------------------------------------------------------------------------
extern "C" void kernel_launch(void* const* d_in, const int* in_sizes, int n_in,
                              void* d_out, int out_size)
{
    const float* x  = (const float*)d_in[0];
    const float* wq = (const float*)d_in[1];
    const float* wk = (const float*)d_in[2];
    const float* wv = (const float*)d_in[3];
    float* out = (float*)d_out;

    cudaFuncSetAttribute(qkv_mma_kernel,
                         cudaFuncAttributeMaxDynamicSharedMemorySize, QKV_SMEM);
    cudaFuncSetAttribute(attn_mma_kernel,
                         cudaFuncAttributeMaxDynamicSharedMemorySize, AT_SMEM);

    const int ntot = N4X + 3 * N4W;
    prep_kernel<<<(ntot + 255) / 256, 256>>>(x, wq, wk, wv);
    qkv_mma_kernel<<<dim3(M_ / 64, H_), 128, QKV_SMEM>>>();
    attn_mma_kernel<<<dim3(S_ / 128, BH_), 128, AT_SMEM>>>(out);
}

// round 17
// speedup vs baseline: 1.0396x; 1.0093x over previous
#include <cuda_runtime.h>
#include <cuda_bf16.h>
#include <cuda_fp16.h>
#include <cstdint>

// Problem constants
#define B_   4
#define S_   2048
#define D_   512
#define H_   8
#define DK_  64
#define BH_  (B_ * H_)      // 32
#define M_   (B_ * S_)      // 8192
// SCALE * log2(e), folded into Q at projection epilogue
#define QSCALE_ (0.18033688011112042f)
#define ONES_F16X2 0x3C003C00u

// fp16 operands (device globals; no allocs allowed)
__device__ __half g_xf[M_ * D_];                  // x single fp16
__device__ __half g_w[3 * D_ * D_];               // Wq,Wk,Wv single fp16
// Attention operands: Q (pre-scaled), K, V — all single fp16
__device__ __half g_qf[BH_ * S_ * DK_];
__device__ __half g_kh[BH_ * S_ * DK_];
__device__ __half g_vh[BH_ * S_ * DK_];

// ---------------------------------------------------------------------------
// helpers
// ---------------------------------------------------------------------------
__device__ __forceinline__ uint32_t pack_f16x2(float x, float y) {
    __half2 h = __floats2half2_rn(x, y);
    return *(uint32_t*)&h;
}
__device__ __forceinline__ uint32_t ex2_f16x2(uint32_t x) {
    uint32_t r;
    asm("ex2.approx.f16x2 %0, %1;" : "=r"(r) : "r"(x));
    return r;
}
__device__ __forceinline__ uint32_t smem_u32(const void* p) {
    uint32_t a;
    asm("{ .reg .u64 t; cvta.to.shared.u64 t, %1; cvt.u32.u64 %0, t; }"
        : "=r"(a) : "l"(p));
    return a;
}
// fp32-accumulator HMMA
__device__ __forceinline__ void mma_f16(float c[4],
        uint32_t a0, uint32_t a1, uint32_t a2, uint32_t a3,
        uint32_t b0, uint32_t b1) {
    asm volatile(
        "mma.sync.aligned.m16n8k16.row.col.f32.f16.f16.f32 "
        "{%0,%1,%2,%3}, {%4,%5,%6,%7}, {%8,%9}, {%0,%1,%2,%3};"
        : "+f"(c[0]), "+f"(c[1]), "+f"(c[2]), "+f"(c[3])
        : "r"(a0), "r"(a1), "r"(a2), "r"(a3), "r"(b0), "r"(b1));
}
// fp16-accumulator HMMA (C/D are 2 regs of packed f16x2)
__device__ __forceinline__ void mma_f16_h(uint32_t c[2],
        uint32_t a0, uint32_t a1, uint32_t a2, uint32_t a3,
        uint32_t b0, uint32_t b1) {
    asm volatile(
        "mma.sync.aligned.m16n8k16.row.col.f16.f16.f16.f16 "
        "{%0,%1}, {%2,%3,%4,%5}, {%6,%7}, {%0,%1};"
        : "+r"(c[0]), "+r"(c[1])
        : "r"(a0), "r"(a1), "r"(a2), "r"(a3), "r"(b0), "r"(b1));
}
__device__ __forceinline__ void ldm_x4(uint32_t& r0, uint32_t& r1,
                                       uint32_t& r2, uint32_t& r3, uint32_t addr) {
    asm volatile("ldmatrix.sync.aligned.m8n8.x4.shared.b16 {%0,%1,%2,%3}, [%4];"
        : "=r"(r0), "=r"(r1), "=r"(r2), "=r"(r3) : "r"(addr));
}
__device__ __forceinline__ void ldm_x4_t(uint32_t& r0, uint32_t& r1,
                                         uint32_t& r2, uint32_t& r3, uint32_t addr) {
    asm volatile("ldmatrix.sync.aligned.m8n8.x4.trans.shared.b16 {%0,%1,%2,%3}, [%4];"
        : "=r"(r0), "=r"(r1), "=r"(r2), "=r"(r3) : "r"(addr));
}
__device__ __forceinline__ void cp16(uint32_t dst, const void* src) {
    asm volatile("cp.async.cg.shared.global [%0], [%1], 16;"
        :: "r"(dst), "l"(src) : "memory");
}
#define CP_COMMIT() asm volatile("cp.async.commit_group;" ::: "memory")
#define CP_WAIT0()  asm volatile("cp.async.wait_group 0;" ::: "memory")

// ---------------------------------------------------------------------------
// Kernel 0: fused prep — convert x and Wq/Wk/Wv to single fp16.
// ---------------------------------------------------------------------------
#define N4X (M_ * D_ / 4)
#define N4W (D_ * D_ / 4)

__global__ __launch_bounds__(256) void prep_kernel(
    const float* __restrict__ x,  const float* __restrict__ wq,
    const float* __restrict__ wk, const float* __restrict__ wv)
{
    int i = blockIdx.x * 256 + threadIdx.x;
    if (i < N4X) {
        float4 v = ((const float4*)x)[i];
        ((uint2*)g_xf)[i] = make_uint2(pack_f16x2(v.x, v.y), pack_f16x2(v.z, v.w));
    } else {
        int j = i - N4X;
        if (j >= 3 * N4W) return;
        int z = j / N4W, jz = j - z * N4W;
        const float* w = (z == 0) ? wq : (z == 1) ? wk : wv;
        float4 v = ((const float4*)w)[jz];
        ((uint2*)(g_w + z * D_ * D_))[jz] =
            make_uint2(pack_f16x2(v.x, v.y), pack_f16x2(v.z, v.w));
    }
}

// ---------------------------------------------------------------------------
// Kernel 1: QKV projection, z-folded, single-term fp16 (unchanged from R16).
// block 128 (4 warps x m16), grid (M/64=128, H=8).
// ---------------------------------------------------------------------------
#define QKV_X  0                // 64 rows * 144B
#define QKV_W  9216             // 3 slices of 64 rows * 144B
#define QKV_STAGE 36864
#define QKV_SMEM (2 * QKV_STAGE)  // 73728

__global__ __launch_bounds__(128) void qkv_mma_kernel()
{
    extern __shared__ char sm[];
    const uint32_t sb = smem_u32(sm);
    const int tid = threadIdx.x, wid = tid >> 5, lane = tid & 31;
    const int g = lane >> 2, c4 = lane & 3;
    const int m0 = blockIdx.x * 64;
    const int h  = blockIdx.y;
    const int n0 = h * 64;

    const uint32_t aAddr = (uint32_t)((wid * 16 + (lane & 15)) * 144 + (lane >> 4) * 16);
    const uint32_t bAddr = (uint32_t)(QKV_W + (lane >> 4) * 1152
                                      + (lane & 7) * 144 + ((lane >> 3) & 1) * 16);

    float o[3][8][4];
#pragma unroll
    for (int z = 0; z < 3; z++)
#pragma unroll
        for (int i = 0; i < 8; i++)
#pragma unroll
            for (int j = 0; j < 4; j++) o[z][i][j] = 0.0f;

    auto copy_stage = [&](int st, int buf) {
        const uint32_t base = sb + buf * QKV_STAGE;
#pragma unroll
        for (int c = tid; c < 2048; c += 128) {
            const void* src;
            uint32_t dst;
            if (c < 512) {
                int row = c >> 3, seg = c & 7;
                src = g_xf + (m0 + row) * D_ + st * 64 + seg * 8;
                dst = base + QKV_X + row * 144 + seg * 16;
            } else {
                int j = c - 512, z = j >> 9, cc = j & 511, row = cc >> 3, seg = cc & 7;
                src = g_w + z * D_ * D_ + (n0 + row) * D_ + st * 64 + seg * 8;
                dst = base + QKV_W + z * 9216 + row * 144 + seg * 16;
            }
            cp16(dst, src);
        }
    };

    copy_stage(0, 0);
    CP_COMMIT();

    for (int st = 0; st < 8; st++) {
        CP_WAIT0();
        __syncthreads();
        if (st < 7) { copy_stage(st + 1, (st + 1) & 1); CP_COMMIT(); }
        const uint32_t base = sb + (st & 1) * QKV_STAGE;
#pragma unroll
        for (int ks = 0; ks < 4; ks++) {
            uint32_t ah[4];
            ldm_x4(ah[0], ah[1], ah[2], ah[3], base + QKV_X + aAddr + ks * 32);
#pragma unroll
            for (int z = 0; z < 3; z++) {
#pragma unroll
                for (int p = 0; p < 4; p++) {
                    uint32_t b0a, b1a, b0b, b1b;
                    ldm_x4(b0a, b1a, b0b, b1b,
                           base + bAddr + z * 9216 + p * 2304 + ks * 32);
                    mma_f16(o[z][2 * p],     ah[0], ah[1], ah[2], ah[3], b0a, b1a);
                    mma_f16(o[z][2 * p + 1], ah[0], ah[1], ah[2], ah[3], b0b, b1b);
                }
            }
        }
    }

    const int r0 = m0 + wid * 16 + g;
    const int r1 = r0 + 8;
    const int b0i = r0 >> 11, s0 = r0 & 2047;
    const int b1i = r1 >> 11, s1 = r1 & 2047;
    const long base0 = ((long)(b0i * H_ + h) * S_ + s0) * DK_;
    const long base1 = ((long)(b1i * H_ + h) * S_ + s1) * DK_;
#pragma unroll
    for (int z = 0; z < 3; z++) {
#pragma unroll
        for (int nt = 0; nt < 8; nt++) {
            const int dk = nt * 8 + c4 * 2;
            if (z == 0) {
                *(uint32_t*)&g_qf[base0 + dk] =
                    pack_f16x2(o[0][nt][0] * QSCALE_, o[0][nt][1] * QSCALE_);
                *(uint32_t*)&g_qf[base1 + dk] =
                    pack_f16x2(o[0][nt][2] * QSCALE_, o[0][nt][3] * QSCALE_);
            } else {
                __half* dst = (z == 1) ? g_kh : g_vh;
                *(uint32_t*)&dst[base0 + dk] = pack_f16x2(o[z][nt][0], o[z][nt][1]);
                *(uint32_t*)&dst[base1 + dk] = pack_f16x2(o[z][nt][2], o[z][nt][3]);
            }
        }
    }
}

// ---------------------------------------------------------------------------
// Kernel 2: attention, TK=128, fp16-acc phase A, copy-free software pipeline:
// phase A of key-group p+1 issues before exp(p) (ping-pong buffers indexed by
// p&1 inside the fully-unrolled loop — static indices, zero register copies).
// grid (S/128=16, BH=32), block 128 (4 warps x m32).
// ---------------------------------------------------------------------------
#define AT_K 0
#define AT_V 18432              // 128 rows * 144B
#define AT_STAGE 36864
#define AT_SMEM (2 * AT_STAGE)  // 73728

__global__ __launch_bounds__(128, 2) void attn_mma_kernel(float* __restrict__ out)
{
    extern __shared__ char sm[];
    const uint32_t sb = smem_u32(sm);
    const int tid = threadIdx.x, wid = tid >> 5, lane = tid & 31;
    const int g = lane >> 2, c4 = lane & 3;
    const int bh = blockIdx.y;
    const int q0 = blockIdx.x * 128;

    const __half* Khg = g_kh + (long)bh * S_ * DK_;
    const __half* Vhg = g_vh + (long)bh * S_ * DK_;
    const __half* Qfg = g_qf + (long)bh * S_ * DK_;

    auto copy_tiles = [&](int kt, int buf) {
        const uint32_t base = sb + buf * AT_STAGE;
#pragma unroll
        for (int c = tid; c < 2048; c += 128) {
            int arr = c >> 10, cc = c & 1023, row = cc >> 3, seg = cc & 7;
            const __half* src = arr ? Vhg : Khg;
            cp16(base + arr * 18432 + row * 144 + seg * 16,
                 src + (kt * 128 + row) * DK_ + seg * 8);
        }
    };

    copy_tiles(0, 0);
    CP_COMMIT();

    uint32_t qf[2][4][4];
#pragma unroll
    for (int rb = 0; rb < 2; rb++) {
        const int r0 = q0 + wid * 32 + rb * 16 + g;
#pragma unroll
        for (int ks = 0; ks < 4; ks++) {
            const int col = ks * 16 + c4 * 2;
            qf[rb][ks][0] = *(const uint32_t*)&Qfg[r0 * DK_ + col];
            qf[rb][ks][1] = *(const uint32_t*)&Qfg[(r0 + 8) * DK_ + col];
            qf[rb][ks][2] = *(const uint32_t*)&Qfg[r0 * DK_ + col + 8];
            qf[rb][ks][3] = *(const uint32_t*)&Qfg[(r0 + 8) * DK_ + col + 8];
        }
    }

    const uint32_t pA = (uint32_t)((lane >> 4) * 1152 + (lane & 7) * 144
                                   + ((lane >> 3) & 1) * 16);
    const uint32_t pB = (uint32_t)(AT_V + (lane & 15) * 144 + (lane >> 4) * 16);

    float o[2][8][4];
#pragma unroll
    for (int rb = 0; rb < 2; rb++)
#pragma unroll
        for (int i = 0; i < 8; i++)
#pragma unroll
            for (int j = 0; j < 4; j++) o[rb][i][j] = 0.0f;
    float dacc[2][4];
#pragma unroll
    for (int rb = 0; rb < 2; rb++)
#pragma unroll
        for (int j = 0; j < 4; j++) dacc[rb][j] = 0.0f;

    // ping-pong fp16-acc score buffers: [buf][rb][n][d]
    uint32_t ehb[2][2][2][2];

    for (int kt = 0; kt < S_ / 128; kt++) {
        CP_WAIT0();
        __syncthreads();
        if (kt < 15) { copy_tiles(kt + 1, (kt + 1) & 1); CP_COMMIT(); }
        const uint32_t base = sb + (kt & 1) * AT_STAGE;

        // phase-A for group p into buffer buf (macro-ish lambda; static buf)
        auto phaseA = [&](int p, uint32_t (&eh)[2][2][2]) {
#pragma unroll
            for (int rb = 0; rb < 2; rb++)
#pragma unroll
                for (int n = 0; n < 2; n++) {
                    eh[rb][n][0] = 0u;
                    eh[rb][n][1] = 0u;
                }
#pragma unroll
            for (int ks = 0; ks < 4; ks++) {
                uint32_t b0a, b1a, b0b, b1b;
                ldm_x4(b0a, b1a, b0b, b1b, base + AT_K + pA + p * 2304 + ks * 32);
#pragma unroll
                for (int rb = 0; rb < 2; rb++) {
                    mma_f16_h(eh[rb][0], qf[rb][ks][0], qf[rb][ks][1], qf[rb][ks][2], qf[rb][ks][3], b0a, b1a);
                    mma_f16_h(eh[rb][1], qf[rb][ks][0], qf[rb][ks][1], qf[rb][ks][2], qf[rb][ks][3], b0b, b1b);
                }
            }
        };

        phaseA(0, ehb[0]);

#pragma unroll
        for (int p = 0; p < 8; p++) {
            // issue next group's score MMAs first — overlaps exp(p) below
            if (p < 7) phaseA(p + 1, ehb[(p + 1) & 1]);

            uint32_t (&eh)[2][2][2] = ehb[p & 1];

            // exp directly on packed f16x2 accumulators; denom via ones-MMA
            uint32_t ph[2][4];
#pragma unroll
            for (int rb = 0; rb < 2; rb++) {
                ph[rb][0] = ex2_f16x2(eh[rb][0][0]);
                ph[rb][1] = ex2_f16x2(eh[rb][0][1]);
                ph[rb][2] = ex2_f16x2(eh[rb][1][0]);
                ph[rb][3] = ex2_f16x2(eh[rb][1][1]);
                mma_f16(dacc[rb], ph[rb][0], ph[rb][1], ph[rb][2], ph[rb][3],
                        ONES_F16X2, ONES_F16X2);
            }

            // PV for key-group p (fp32 accumulators)
#pragma unroll
            for (int pp = 0; pp < 4; pp++) {
                uint32_t b0a, b1a, b0b, b1b;
                ldm_x4_t(b0a, b1a, b0b, b1b, base + pB + p * 2304 + pp * 32);
#pragma unroll
                for (int rb = 0; rb < 2; rb++) {
                    mma_f16(o[rb][2 * pp],     ph[rb][0], ph[rb][1], ph[rb][2], ph[rb][3], b0a, b1a);
                    mma_f16(o[rb][2 * pp + 1], ph[rb][0], ph[rb][1], ph[rb][2], ph[rb][3], b0b, b1b);
                }
            }
        }
    }

    const int b = bh >> 3, h = bh & 7;
#pragma unroll
    for (int rb = 0; rb < 2; rb++) {
        const float inv0 = 1.0f / (dacc[rb][0] + 1e-8f);
        const float inv1 = 1.0f / (dacc[rb][2] + 1e-8f);

        const int q_r0 = q0 + wid * 32 + rb * 16 + g;
        float* op0 = &out[((long)(b * S_ + q_r0)) * D_ + h * 64];
        float* op1 = &out[((long)(b * S_ + q_r0 + 8)) * D_ + h * 64];
#pragma unroll
        for (int nt = 0; nt < 8; nt++) {
            const int dk = nt * 8 + c4 * 2;
            *(float2*)&op0[dk] = make_float2(o[rb][nt][0] * inv0, o[rb][nt][1] * inv0);
            *(float2*)&op1[dk] = make_float2(o[rb][nt][2] * inv1, o[rb][nt][3] * inv1);
        }
    }
}

// ---------------------------------------------------------------------------
extern "C" void kernel_launch(void* const* d_in, const int* in_sizes, int n_in,
                              void* d_out, int out_size)
{
    const float* x  = (const float*)d_in[0];
    const float* wq = (const float*)d_in[1];
    const float* wk = (const float*)d_in[2];
    const float* wv = (const float*)d_in[3];
    float* out = (float*)d_out;

    cudaFuncSetAttribute(qkv_mma_kernel,
                         cudaFuncAttributeMaxDynamicSharedMemorySize, QKV_SMEM);
    cudaFuncSetAttribute(attn_mma_kernel,
                         cudaFuncAttributeMaxDynamicSharedMemorySize, AT_SMEM);

    const int ntot = N4X + 3 * N4W;
    prep_kernel<<<(ntot + 255) / 256, 256>>>(x, wq, wk, wv);
    qkv_mma_kernel<<<dim3(M_ / 64, H_), 128, QKV_SMEM>>>();
    attn_mma_kernel<<<dim3(S_ / 128, BH_), 128, AT_SMEM>>>(out);
}